// round 12
// baseline (speedup 1.0000x reference)
#include <cuda_runtime.h>

// Fused 3-layer GraphConv, B=524288.
//   A_ENC:  agg[j]  = sum_{i=4j-3..4j+2} x[i mod 40]
//   A_PRED: agg2[j] = z1[j] + w*(z1[j-1] + z1[j+1]),  w = exp(-1/9)
//   A_DEC:  out[4k]=s[k], out[4k+1]=out[4k+2]=s[k]+s[k+1], out[4k+3]=s[k+1]
//           with s[j] = dot(relu(pred(z1)[j]), dec_rel_w)
//
// R11 vs R10 (138us total / 132us kernel, issue-bound at 46.7%):
//  - enc->pred software pipeline in registers: z1 never returns to smem
//    (kills 20 STS.128 + 24 LDS.128 per thread, ~40% of shared ops).
//    Scalar + constant weights keeps the window affordable (R2's f32x2
//    version of this idea spilled; weights-in-UR changes the math).
//  - everything else per R10: constant weights via gather+1 memcpy,
//    full-block specialization, volatile LDS anti-hoist on staging reads.

#define WPRED 0.8948393168143698f

__constant__ __align__(16) float cW[232];
#define C_ER  0     // enc_root_w  [f*8+g]
#define C_PR  64    // pred_rel_w
#define C_PO  128   // pred_root_w
#define C_ERW 192
#define C_ERB 200
#define C_PRB 208
#define C_DRW 216
#define C_DRB 224
#define C_DRT 225

__device__ __align__(16) float gStage[232];

__global__ void gather_weights(const float* __restrict__ erw, const float* __restrict__ erb,
                               const float* __restrict__ er,  const float* __restrict__ pr,
                               const float* __restrict__ prb, const float* __restrict__ po,
                               const float* __restrict__ drw, const float* __restrict__ drb,
                               const float* __restrict__ drt)
{
    const int t = threadIdx.x;
    if (t < 64) {
        gStage[C_ER + t] = er[t];
        gStage[C_PR + t] = pr[t];
        gStage[C_PO + t] = po[t];
    }
    if (t < 8) {
        gStage[C_ERW + t] = erw[t];
        gStage[C_ERB + t] = erb[t];
        gStage[C_PRB + t] = prb[t];
        gStage[C_DRW + t] = drw[t];
    }
    if (t == 0) { gStage[C_DRB] = drb[0]; gStage[C_DRT] = drt[0]; }
}

__device__ __forceinline__ float4 lds128a(unsigned a) {
    float4 r;
    asm volatile("ld.shared.v4.f32 {%0,%1,%2,%3}, [%4];"
                 : "=f"(r.x), "=f"(r.y), "=f"(r.z), "=f"(r.w) : "r"(a));
    return r;
}
__device__ __forceinline__ unsigned saddr(const void* p) {
    return (unsigned)__cvta_generic_to_shared(p);
}

// encoder for one node: z row from smem (volatile), weights from constant,
// result in registers (float4 pair)
__device__ __forceinline__ void enc_node(unsigned zr_a, int j, float aggj,
                                         float4& oa, float4& ob)
{
    float4 a = lds128a(zr_a + j * 32);
    float4 b = lds128a(zr_a + j * 32 + 16);
    const float4* er4 = (const float4*)(cW + C_ER);
    float t[8];
    #pragma unroll
    for (int f = 0; f < 8; f++) {
        float4 w0 = er4[f * 2], w1 = er4[f * 2 + 1];
        float c0 = fmaf(a.x, w0.x, fmaf(a.y, w0.y,
                   fmaf(a.z, w0.z, fmaf(a.w, w0.w,
                   fmaf(aggj, cW[C_ERW + f], cW[C_ERB + f])))));
        float c1 = fmaf(b.x, w1.x, fmaf(b.y, w1.y, fmaf(b.z, w1.z, b.w * w1.w)));
        t[f] = fmaxf(c0 + c1, 0.0f);
    }
    oa = make_float4(t[0], t[1], t[2], t[3]);
    ob = make_float4(t[4], t[5], t[6], t[7]);
}

// predictor node + dec_rel fold, split accumulator chains, constant weights
__device__ __forceinline__ float pred_s(float4 ma, float4 mb, float4 ca, float4 cb,
                                        float4 na, float4 nb)
{
    float4 Aa, Ab;
    Aa.x = fmaf(WPRED, ma.x + na.x, ca.x);
    Aa.y = fmaf(WPRED, ma.y + na.y, ca.y);
    Aa.z = fmaf(WPRED, ma.z + na.z, ca.z);
    Aa.w = fmaf(WPRED, ma.w + na.w, ca.w);
    Ab.x = fmaf(WPRED, mb.x + nb.x, cb.x);
    Ab.y = fmaf(WPRED, mb.y + nb.y, cb.y);
    Ab.z = fmaf(WPRED, mb.z + nb.z, cb.z);
    Ab.w = fmaf(WPRED, mb.w + nb.w, cb.w);
    const float4* pr4 = (const float4*)(cW + C_PR);
    const float4* po4 = (const float4*)(cW + C_PO);
    float sj0 = 0.0f, sj1 = 0.0f;
    #pragma unroll
    for (int f = 0; f < 8; f++) {
        float4 r0 = pr4[f * 2], r1 = pr4[f * 2 + 1];
        float4 o0 = po4[f * 2], o1 = po4[f * 2 + 1];
        float p0 = fmaf(Aa.x, r0.x, fmaf(Aa.y, r0.y, fmaf(Aa.z, r0.z, fmaf(Aa.w, r0.w, cW[C_PRB + f]))));
        float p1 = fmaf(Ab.x, r1.x, fmaf(Ab.y, r1.y, fmaf(Ab.z, r1.z, Ab.w * r1.w)));
        float p2 = fmaf(ca.x, o0.x, fmaf(ca.y, o0.y, fmaf(ca.z, o0.z, ca.w * o0.w)));
        float p3 = fmaf(cb.x, o1.x, fmaf(cb.y, o1.y, fmaf(cb.z, o1.z, cb.w * o1.w)));
        float r = fmaxf((p0 + p1) + (p2 + p3), 0.0f);
        if (f & 1) sj1 = fmaf(r, cW[C_DRW + f], sj1);
        else       sj0 = fmaf(r, cW[C_DRW + f], sj0);
    }
    return sj0 + sj1;
}

template <bool FULL>
__device__ __forceinline__ void body(const float* __restrict__ x,
                                     const float* __restrict__ z,
                                     const float* __restrict__ y,
                                     float* __restrict__ out,
                                     float* buf, int lane, long long e0, int nv)
{
    float* ss = buf;   // alias: reused after z is consumed (32 x stride-11 floats)

    // ===== stage x (coalesced, streaming), rows padded to 44 floats =====
    {
        const float4* xg = (const float4*)(x + e0 * 40);
        const int lim = nv * 10;
        #pragma unroll
        for (int k = 0; k < 10; k++) {
            int f4 = k * 32 + lane;
            if (FULL || f4 < lim) {
                float4 v = __ldcs(&xg[f4]);
                *(float4*)&buf[(f4 / 10) * 44 + (f4 % 10) * 4] = v;
            }
        }
    }
    __syncwarp();

    // agg[j] = (last 3 of float4[j-1]) + (first 3 of float4[j]), rolling window
    float agg[10];
    if (FULL || lane < nv) {
        const unsigned mx = saddr(&buf[lane * 44]);
        float4 vp = lds128a(mx + 9 * 16);
        #pragma unroll
        for (int j = 0; j < 10; j++) {
            float4 v = lds128a(mx + j * 16);
            agg[j] = (vp.y + vp.z) + (vp.w + v.x) + (v.y + v.z);
            vp = v;
        }
    }
    __syncwarp();

    // ===== stage z (coalesced, streaming), rows padded to 84 floats =====
    {
        const float4* zg = (const float4*)(z + e0 * 80);
        const int lim = nv * 20;
        #pragma unroll
        for (int k = 0; k < 20; k++) {
            int f4 = k * 32 + lane;
            if (FULL || f4 < lim) {
                float4 v = __ldcs(&zg[f4]);
                *(float4*)&buf[(f4 / 20) * 84 + (f4 % 20) * 4] = v;
            }
        }
    }
    __syncwarp();

    float s[10];
    if (FULL || lane < nv) {
        const unsigned zr_a = saddr(&buf[lane * 84]);

        // enc->pred software pipeline; z1 lives only in the rolling window.
        float4 Z0a, Z0b, Z1a, Z1b;            // saved z1[0], z1[1] for wrap
        float4 maA, maB, caA, caB, naA, naB;  // window z1[j-1], z1[j], z1[j+1]
        enc_node(zr_a, 0, agg[0], Z0a, Z0b);
        enc_node(zr_a, 1, agg[1], Z1a, Z1b);
        maA = Z0a; maB = Z0b; caA = Z1a; caB = Z1b;
        #pragma unroll
        for (int j = 1; j <= 8; j++) {
            enc_node(zr_a, j + 1, agg[j + 1], naA, naB);
            s[j] = pred_s(maA, maB, caA, caB, naA, naB);
            maA = caA; maB = caB; caA = naA; caB = naB;
        }
        // window: ma=z1[8], ca=z1[9]
        s[9] = pred_s(maA, maB, caA, caB, Z0a, Z0b);
        s[0] = pred_s(caA, caB, Z0a, Z0b, Z1a, Z1b);
    }
    __syncwarp();   // all reads of z staging done -> safe to overwrite via alias

    if (FULL || lane < nv) {
        #pragma unroll
        for (int j = 0; j < 10; j++)
            ss[lane * 11 + j] = s[j];
    }
    __syncwarp();

    // ===== decoder: y streamed from gmem, out written directly, coalesced =====
    {
        const float4* yg = (const float4*)(y + e0 * 40);
        float4* og = (float4*)(out + e0 * 40);
        const float drb = cW[C_DRB], drt = cW[C_DRT];
        const int lim = nv * 10;
        #pragma unroll
        for (int k = 0; k < 10; k++) {
            int f4 = k * 32 + lane;
            if (FULL || f4 < lim) {
                const int e = f4 / 10, c = f4 % 10;
                float4 v = __ldcs(&yg[f4]);
                const float s0 = ss[e * 11 + c];
                const float s1 = ss[e * 11 + ((c + 1) % 10)];
                const float c12 = s0 + s1;
                v.x = fmaf(v.x, drt, drb) + s0;
                v.y = fmaf(v.y, drt, drb) + c12;
                v.z = fmaf(v.z, drt, drb) + c12;
                v.w = fmaf(v.w, drt, drb) + s1;
                __stcs(&og[f4], v);
            }
        }
    }
}

__global__ void __launch_bounds__(128, 5)
fused_gnn_kernel(const float* __restrict__ x,
                 const float* __restrict__ z,
                 const float* __restrict__ y,
                 float* __restrict__ out,
                 long long B)
{
    __shared__ __align__(16) float4 sbuf4[4][672];  // per warp: 32 rows x 84 floats

    const int tid = threadIdx.x;
    const int warp = tid >> 5;
    const int lane = tid & 31;
    const long long e0 = ((long long)blockIdx.x * 4 + warp) * 32;
    if (e0 >= B) return;
    float* buf = (float*)sbuf4[warp];

    if (B - e0 >= 32) {
        body<true>(x, z, y, out, buf, lane, e0, 32);
    } else {
        body<false>(x, z, y, out, buf, lane, e0, (int)(B - e0));
    }
}

extern "C" void kernel_launch(void* const* d_in, const int* in_sizes, int n_in,
                              void* d_out, int out_size)
{
    const float* x = (const float*)d_in[0];
    const float* z = (const float*)d_in[1];
    const float* y = (const float*)d_in[2];

    // 1) pack all weights into contiguous device staging (one kernel node)
    gather_weights<<<1, 64>>>(
        (const float*)d_in[3], (const float*)d_in[4], (const float*)d_in[5],
        (const float*)d_in[6], (const float*)d_in[7], (const float*)d_in[8],
        (const float*)d_in[9], (const float*)d_in[10], (const float*)d_in[11]);

    // 2) one D2D memcpy into __constant__ (graph-capturable)
    void* stage_ptr = nullptr;
    cudaGetSymbolAddress(&stage_ptr, gStage);
    cudaMemcpyToSymbolAsync(cW, stage_ptr, 232 * sizeof(float), 0,
                            cudaMemcpyDeviceToDevice, 0);

    const long long B = (long long)in_sizes[0] / 40;
    const int threads = 128;                      // 4 warps x 32 elements
    const long long elems_per_block = 128;
    const int blocks = (int)((B + elems_per_block - 1) / elems_per_block);

    fused_gnn_kernel<<<blocks, threads>>>(x, z, y, (float*)d_out, B);
}

// round 13
// speedup vs baseline: 1.3246x; 1.3246x over previous
#include <cuda_runtime.h>

// Fused 3-layer GraphConv, B=524288.
//   A_ENC:  agg[j]  = sum_{i=4j-3..4j+2} x[i mod 40]
//   A_PRED: agg2[j] = z1[j] + w*(z1[j-1] + z1[j+1]),  w = exp(-1/9)
//   A_DEC:  out[4k]=s[k], out[4k+1]=out[4k+2]=s[k]+s[k+1], out[4k+3]=s[k+1]
//           with s[j] = dot(relu(pred(z1)[j]), dec_rel_w)
//
// R12 = R10 (best structure, 138us) + pred-phase algebra/blocking:
//  - M1 = PR+PO, M2 = w*PR precomputed in gather kernel:
//      t_j = M1@z1_j + M2@(z1_{j-1}+z1_{j+1}) + prb   (a2 eliminated)
//  - 2-node blocking, 4-row rolling window: one weight fetch per f serves
//    two nodes (pred LDCU.128 halved); ring wrap handled uniformly (mod 10).
//  - R11's cross-phase register pipeline REVERTED (it issued +50% instr).

#define WPRED 0.8948393168143698f

__constant__ __align__(16) float cW[232];
#define C_ER  0     // enc_root_w  [f*8+g]
#define C_M1  64    // PR + PO
#define C_M2  128   // WPRED * PR
#define C_ERW 192
#define C_ERB 200
#define C_PRB 208
#define C_DRW 216
#define C_DRB 224
#define C_DRT 225

__device__ __align__(16) float gStage[232];

__global__ void gather_weights(const float* __restrict__ erw, const float* __restrict__ erb,
                               const float* __restrict__ er,  const float* __restrict__ pr,
                               const float* __restrict__ prb, const float* __restrict__ po,
                               const float* __restrict__ drw, const float* __restrict__ drb,
                               const float* __restrict__ drt)
{
    const int t = threadIdx.x;
    if (t < 64) {
        gStage[C_ER + t] = er[t];
        gStage[C_M1 + t] = pr[t] + po[t];
        gStage[C_M2 + t] = WPRED * pr[t];
    }
    if (t < 8) {
        gStage[C_ERW + t] = erw[t];
        gStage[C_ERB + t] = erb[t];
        gStage[C_PRB + t] = prb[t];
        gStage[C_DRW + t] = drw[t];
    }
    if (t == 0) { gStage[C_DRB] = drb[0]; gStage[C_DRT] = drt[0]; }
}

__device__ __forceinline__ float4 lds128a(unsigned a) {
    float4 r;
    asm volatile("ld.shared.v4.f32 {%0,%1,%2,%3}, [%4];"
                 : "=f"(r.x), "=f"(r.y), "=f"(r.z), "=f"(r.w) : "r"(a));
    return r;
}
__device__ __forceinline__ void sts128a(unsigned a, float4 v) {
    asm volatile("st.shared.v4.f32 [%0], {%1,%2,%3,%4};"
                 :: "r"(a), "f"(v.x), "f"(v.y), "f"(v.z), "f"(v.w));
}
__device__ __forceinline__ unsigned saddr(const void* p) {
    return (unsigned)__cvta_generic_to_shared(p);
}

template <bool FULL>
__device__ __forceinline__ void body(const float* __restrict__ x,
                                     const float* __restrict__ z,
                                     const float* __restrict__ y,
                                     float* __restrict__ out,
                                     float* buf, int lane, long long e0, int nv)
{
    float* ss = buf;   // alias: reused after z1 dead (32 x stride-11 floats)

    // ===== stage x (coalesced, streaming), rows padded to 44 floats =====
    {
        const float4* xg = (const float4*)(x + e0 * 40);
        const int lim = nv * 10;
        #pragma unroll
        for (int k = 0; k < 10; k++) {
            int f4 = k * 32 + lane;
            if (FULL || f4 < lim) {
                float4 v = __ldcs(&xg[f4]);
                *(float4*)&buf[(f4 / 10) * 44 + (f4 % 10) * 4] = v;
            }
        }
    }
    __syncwarp();

    // agg[j] = (last 3 of float4[j-1]) + (first 3 of float4[j]), rolling window
    float agg[10];
    if (FULL || lane < nv) {
        const unsigned mx = saddr(&buf[lane * 44]);
        float4 vp = lds128a(mx + 9 * 16);
        #pragma unroll
        for (int j = 0; j < 10; j++) {
            float4 v = lds128a(mx + j * 16);
            agg[j] = (vp.y + vp.z) + (vp.w + v.x) + (v.y + v.z);
            vp = v;
        }
    }
    __syncwarp();

    // ===== stage z (coalesced, streaming), rows padded to 84 floats =====
    {
        const float4* zg = (const float4*)(z + e0 * 80);
        const int lim = nv * 20;
        #pragma unroll
        for (int k = 0; k < 20; k++) {
            int f4 = k * 32 + lane;
            if (FULL || f4 < lim) {
                float4 v = __ldcs(&zg[f4]);
                *(float4*)&buf[(f4 / 20) * 84 + (f4 % 20) * 4] = v;
            }
        }
    }
    __syncwarp();

    float s[10];
    if (FULL || lane < nv) {
        const unsigned zr_a = saddr(&buf[lane * 84]);
        const float4* er4 = (const float4*)(cW + C_ER);

        // ---- encoder: z1[j] overwrites z[j] in smem, split chains ----
        #pragma unroll
        for (int j = 0; j < 10; j++) {
            float4 a = lds128a(zr_a + j * 32);
            float4 b = lds128a(zr_a + j * 32 + 16);
            float t[8];
            #pragma unroll
            for (int f = 0; f < 8; f++) {
                float4 w0 = er4[f * 2], w1 = er4[f * 2 + 1];
                float c0 = fmaf(a.x, w0.x, fmaf(a.y, w0.y,
                           fmaf(a.z, w0.z, fmaf(a.w, w0.w,
                           fmaf(agg[j], cW[C_ERW + f], cW[C_ERB + f])))));
                float c1 = fmaf(b.x, w1.x, fmaf(b.y, w1.y, fmaf(b.z, w1.z, b.w * w1.w)));
                t[f] = fmaxf(c0 + c1, 0.0f);
            }
            sts128a(zr_a + j * 32,      make_float4(t[0], t[1], t[2], t[3]));
            sts128a(zr_a + j * 32 + 16, make_float4(t[4], t[5], t[6], t[7]));
        }

        // ---- predictor: 2-node blocking, 4-row rolling window ----
        // nodes (2p+1, 2p+2): t = M1@center + M2@(neighbor sum) + prb
        const float4* m14 = (const float4*)(cW + C_M1);
        const float4* m24 = (const float4*)(cW + C_M2);
        float4 r0a = lds128a(zr_a + 0);        // z1[0]
        float4 r0b = lds128a(zr_a + 16);
        float4 r1a = lds128a(zr_a + 32);       // z1[1]
        float4 r1b = lds128a(zr_a + 48);
        #pragma unroll
        for (int p = 0; p < 5; p++) {
            const int n1 = (2 * p + 1) % 10;   // node indices
            const int n2 = (2 * p + 2) % 10;
            const int i2 = (2 * p + 2) % 10;   // row indices to load
            const int i3 = (2 * p + 3) % 10;
            float4 r2a = lds128a(zr_a + i2 * 32);
            float4 r2b = lds128a(zr_a + i2 * 32 + 16);
            float4 r3a = lds128a(zr_a + i3 * 32);
            float4 r3b = lds128a(zr_a + i3 * 32 + 16);
            // neighbor sums
            float4 u1a = make_float4(r0a.x + r2a.x, r0a.y + r2a.y, r0a.z + r2a.z, r0a.w + r2a.w);
            float4 u1b = make_float4(r0b.x + r2b.x, r0b.y + r2b.y, r0b.z + r2b.z, r0b.w + r2b.w);
            float4 u2a = make_float4(r1a.x + r3a.x, r1a.y + r3a.y, r1a.z + r3a.z, r1a.w + r3a.w);
            float4 u2b = make_float4(r1b.x + r3b.x, r1b.y + r3b.y, r1b.z + r3b.z, r1b.w + r3b.w);
            float s1e = 0.0f, s1o = 0.0f, s2e = 0.0f, s2o = 0.0f;
            #pragma unroll
            for (int f = 0; f < 8; f++) {
                float4 a0 = m14[f * 2], a1 = m14[f * 2 + 1];
                float4 b0 = m24[f * 2], b1 = m24[f * 2 + 1];
                const float bias = cW[C_PRB + f];
                const float dw   = cW[C_DRW + f];
                // node n1: center (r1), nsum (u1)
                float p0 = fmaf(r1a.x, a0.x, fmaf(r1a.y, a0.y, fmaf(r1a.z, a0.z, fmaf(r1a.w, a0.w, bias))));
                float p1 = fmaf(r1b.x, a1.x, fmaf(r1b.y, a1.y, fmaf(r1b.z, a1.z, r1b.w * a1.w)));
                float p2 = fmaf(u1a.x, b0.x, fmaf(u1a.y, b0.y, fmaf(u1a.z, b0.z, u1a.w * b0.w)));
                float p3 = fmaf(u1b.x, b1.x, fmaf(u1b.y, b1.y, fmaf(u1b.z, b1.z, u1b.w * b1.w)));
                float t1 = fmaxf((p0 + p1) + (p2 + p3), 0.0f);
                // node n2: center (r2), nsum (u2)
                float q0 = fmaf(r2a.x, a0.x, fmaf(r2a.y, a0.y, fmaf(r2a.z, a0.z, fmaf(r2a.w, a0.w, bias))));
                float q1 = fmaf(r2b.x, a1.x, fmaf(r2b.y, a1.y, fmaf(r2b.z, a1.z, r2b.w * a1.w)));
                float q2 = fmaf(u2a.x, b0.x, fmaf(u2a.y, b0.y, fmaf(u2a.z, b0.z, u2a.w * b0.w)));
                float q3 = fmaf(u2b.x, b1.x, fmaf(u2b.y, b1.y, fmaf(u2b.z, b1.z, u2b.w * b1.w)));
                float t2 = fmaxf((q0 + q1) + (q2 + q3), 0.0f);
                if (f & 1) { s1o = fmaf(t1, dw, s1o); s2o = fmaf(t2, dw, s2o); }
                else       { s1e = fmaf(t1, dw, s1e); s2e = fmaf(t2, dw, s2e); }
            }
            s[n1] = s1e + s1o;
            s[n2] = s2e + s2o;
            r0a = r2a; r0b = r2b; r1a = r3a; r1b = r3b;
        }
    }
    __syncwarp();   // all pred reads of z1 done -> safe to overwrite via alias

    if (FULL || lane < nv) {
        #pragma unroll
        for (int j = 0; j < 10; j++)
            ss[lane * 11 + j] = s[j];
    }
    __syncwarp();

    // ===== decoder: y streamed from gmem, out written directly, coalesced =====
    {
        const float4* yg = (const float4*)(y + e0 * 40);
        float4* og = (float4*)(out + e0 * 40);
        const float drb = cW[C_DRB], drt = cW[C_DRT];
        const int lim = nv * 10;
        #pragma unroll
        for (int k = 0; k < 10; k++) {
            int f4 = k * 32 + lane;
            if (FULL || f4 < lim) {
                const int e = f4 / 10, c = f4 % 10;
                float4 v = __ldcs(&yg[f4]);
                const float s0 = ss[e * 11 + c];
                const float s1 = ss[e * 11 + ((c + 1) % 10)];
                const float c12 = s0 + s1;
                v.x = fmaf(v.x, drt, drb) + s0;
                v.y = fmaf(v.y, drt, drb) + c12;
                v.z = fmaf(v.z, drt, drb) + c12;
                v.w = fmaf(v.w, drt, drb) + s1;
                __stcs(&og[f4], v);
            }
        }
    }
}

__global__ void __launch_bounds__(128, 5)
fused_gnn_kernel(const float* __restrict__ x,
                 const float* __restrict__ z,
                 const float* __restrict__ y,
                 float* __restrict__ out,
                 long long B)
{
    __shared__ __align__(16) float4 sbuf4[4][672];  // per warp: 32 rows x 84 floats

    const int tid = threadIdx.x;
    const int warp = tid >> 5;
    const int lane = tid & 31;
    const long long e0 = ((long long)blockIdx.x * 4 + warp) * 32;
    if (e0 >= B) return;
    float* buf = (float*)sbuf4[warp];

    if (B - e0 >= 32) {
        body<true>(x, z, y, out, buf, lane, e0, 32);
    } else {
        body<false>(x, z, y, out, buf, lane, e0, (int)(B - e0));
    }
}

extern "C" void kernel_launch(void* const* d_in, const int* in_sizes, int n_in,
                              void* d_out, int out_size)
{
    const float* x = (const float*)d_in[0];
    const float* z = (const float*)d_in[1];
    const float* y = (const float*)d_in[2];

    // 1) pack + pre-transform weights into contiguous device staging
    gather_weights<<<1, 64>>>(
        (const float*)d_in[3], (const float*)d_in[4], (const float*)d_in[5],
        (const float*)d_in[6], (const float*)d_in[7], (const float*)d_in[8],
        (const float*)d_in[9], (const float*)d_in[10], (const float*)d_in[11]);

    // 2) one D2D memcpy into __constant__ (graph-capturable)
    void* stage_ptr = nullptr;
    cudaGetSymbolAddress(&stage_ptr, gStage);
    cudaMemcpyToSymbolAsync(cW, stage_ptr, 232 * sizeof(float), 0,
                            cudaMemcpyDeviceToDevice, 0);

    const long long B = (long long)in_sizes[0] / 40;
    const int threads = 128;                      // 4 warps x 32 elements
    const long long elems_per_block = 128;
    const int blocks = (int)((B + elems_per_block - 1) / elems_per_block);

    fused_gnn_kernel<<<blocks, threads>>>(x, z, y, (float*)d_out, B);
}